// round 17
// baseline (speedup 1.0000x reference)
#include <cuda_runtime.h>
#include <cuda_fp16.h>
#include <cstdint>

#define BB 16
#define CC 256
#define HH 96
#define WW 96
#define QKD 64
#define PP (HH*WW)          // 9216
#define JTOT 384

// ---------------- scratch (static device memory; no allocs allowed) ----------
__device__ float g_bcat[JTOT];
__device__ __half g_Whi[JTOT*CC];
__device__ __half g_Qhi[(size_t)BB*WW*HH*QKD];
__device__ __half g_Khi[(size_t)BB*WW*HH*QKD];
__device__ __half g_Vhi[(size_t)BB*WW*HH*CC];
__device__ __half g_Ot[(size_t)BB*WW*HH*CC];

// ---------------- PTX helpers (baseline, sm_103-safe) ------------------------
__device__ __forceinline__ uint32_t smem_u32(const void* p) {
    uint32_t a;
    asm("{ .reg .u64 t; cvta.to.shared.u64 t, %1; cvt.u32.u64 %0, t; }" : "=r"(a) : "l"(p));
    return a;
}
__device__ __forceinline__ void ldsm_x4(uint32_t* r, uint32_t addr) {
    asm volatile("ldmatrix.sync.aligned.m8n8.x4.shared.b16 {%0,%1,%2,%3}, [%4];"
        : "=r"(r[0]), "=r"(r[1]), "=r"(r[2]), "=r"(r[3]) : "r"(addr));
}
__device__ __forceinline__ void ldsm_x4t(uint32_t* r, uint32_t addr) {
    asm volatile("ldmatrix.sync.aligned.m8n8.x4.trans.shared.b16 {%0,%1,%2,%3}, [%4];"
        : "=r"(r[0]), "=r"(r[1]), "=r"(r[2]), "=r"(r[3]) : "r"(addr));
}
__device__ __forceinline__ void ldsm_x2(uint32_t* r, uint32_t addr) {
    asm volatile("ldmatrix.sync.aligned.m8n8.x2.shared.b16 {%0,%1}, [%2];"
        : "=r"(r[0]), "=r"(r[1]) : "r"(addr));
}
__device__ __forceinline__ void mma_h(float* d, const uint32_t* a, const uint32_t* b) {
    asm volatile("mma.sync.aligned.m16n8k16.row.col.f32.f16.f16.f32 "
        "{%0,%1,%2,%3}, {%4,%5,%6,%7}, {%8,%9}, {%0,%1,%2,%3};"
        : "+f"(d[0]), "+f"(d[1]), "+f"(d[2]), "+f"(d[3])
        : "r"(a[0]), "r"(a[1]), "r"(a[2]), "r"(a[3]), "r"(b[0]), "r"(b[1]));
}
#define CP_ASYNC16(dst, src) \
    asm volatile("cp.async.cg.shared.global [%0], [%1], 16;" :: "r"(dst), "l"(src))
#define CP_COMMIT() asm volatile("cp.async.commit_group;" ::: "memory")
#define CP_WAIT0()  asm volatile("cp.async.wait_group 0;" ::: "memory")
#define CP_WAIT1()  asm volatile("cp.async.wait_group 1;" ::: "memory")
#define CP_WAIT2()  asm volatile("cp.async.wait_group 2;" ::: "memory")

// ---------------- kernel 0: weight concat (fp16 hi only) ---------------------
__global__ void prep_kernel(const float* __restrict__ Wq, const float* __restrict__ bq,
                            const float* __restrict__ Wk, const float* __restrict__ bk,
                            const float* __restrict__ Wv, const float* __restrict__ bv) {
    int i = blockIdx.x * blockDim.x + threadIdx.x;
    if (i < JTOT*CC) {
        int j = i / CC, k = i % CC;
        float v;
        if (j < 64)       v = Wq[j*CC + k];
        else if (j < 128) v = Wk[(j-64)*CC + k];
        else              v = Wv[(j-128)*CC + k];
        g_Whi[i] = __float2half_rn(v);
    }
    if (i < JTOT) {
        g_bcat[i] = (i < 64) ? bq[i] : (i < 128) ? bk[i-64] : bv[i-128];
    }
}

// ---------------- kernel 1: QKV projection (fp16 warp MMA, 1-pass) -----------
#define OFF_BH   0
#define OFF_A    32768      // 3 x 8192
#define OFF_STG  57344      // 64 x 68 fp32 = 17408
#define OFF_BIAS 74752
#define QKV_SMEM 76288
#define STGP 68

__global__ __launch_bounds__(256, 3) void qkv_mma_kernel(const float* __restrict__ x) {
    extern __shared__ __align__(128) char smq[];
    uint32_t sb = smem_u32(smq);
    int tid = threadIdx.x, wid = tid >> 5, lane = tid & 31;
    int pBase = blockIdx.x * 64;
    int bz = blockIdx.y;
    int warpM = wid & 1, warpN = wid >> 1;
    int jW = warpM * 32, pW = warpN * 16;

    for (int t = tid; t < JTOT; t += 256)
        *(float*)(smq + OFF_BIAS + t*4) = g_bcat[t];

    #pragma unroll
    for (int pre = 0; pre < 2; pre++) {
        const __half* sH = g_Whi + pre*64;
        uint32_t dst = sb + OFF_A + (uint32_t)(pre * 8192);
        for (int t = tid; t < 512; t += 256) {
            int j = t >> 3, sg = t & 7;
            uint32_t sw = (uint32_t)(j*128 + ((sg ^ (j & 7))*16));
            CP_ASYNC16(dst + sw, sH + j*CC + sg*8);
        }
        CP_COMMIT();
    }

    {
        const float* xb = x + (size_t)bz*CC*PP;
        for (int t = tid; t < 4096; t += 256) {
            int k = t >> 4, sg = t & 15;
            float4 v = *(const float4*)&xb[(size_t)k*PP + pBase + sg*4];
            __half2 h0 = __float22half2_rn(make_float2(v.x, v.y));
            __half2 h1 = __float22half2_rn(make_float2(v.z, v.w));
            uint32_t sw = (uint32_t)(k*128 + (((sg>>1) ^ (k & 7))*16) + (sg&1)*8);
            *(uint2*)(smq + OFF_BH + sw) = make_uint2(*(uint32_t*)&h0, *(uint32_t*)&h1);
        }
    }

    int rA   = lane & 15;
    int swzA = rA & 7;
    int aseg = lane >> 4;
    int swzB = lane & 7;
    int bseg = (pW >> 3);
    int rq = lane >> 2, c2 = (lane & 3) * 2;

    for (int jt = 0; jt < 6; jt++) {
        float acc[2][2][4] = {};

        for (int ch = 0; ch < 4; ch++) {
            int it = jt*4 + ch;
            if (it == 23) { CP_WAIT0(); } else { CP_WAIT1(); }
            __syncthreads();
            int nit = it + 2;
            if (nit < 24) {
                int njt = nit >> 2, nch = nit & 3;
                uint32_t dst = sb + OFF_A + (uint32_t)((nit % 3) * 8192);
                const __half* sH = g_Whi + (njt*64)*CC + nch*64;
                for (int t = tid; t < 512; t += 256) {
                    int j = t >> 3, sg = t & 7;
                    uint32_t sw = (uint32_t)(j*128 + ((sg ^ (j & 7))*16));
                    CP_ASYNC16(dst + sw, sH + j*CC + sg*8);
                }
                CP_COMMIT();
            }
            uint32_t aBufH = sb + OFF_A + (uint32_t)((it % 3) * 8192);

            #pragma unroll
            for (int ksc = 0; ksc < 4; ksc++) {
                int ks16 = ch*4 + ksc;
                uint32_t brow = (uint32_t)((ks16*16 + rA)*128 + (((bseg + aseg) ^ swzB)*16));
                uint32_t ah[2][4], bh4[4];
                #pragma unroll
                for (int mi = 0; mi < 2; mi++) {
                    int row = jW + rA + mi*16;
                    ldsm_x4(ah[mi], aBufH + (uint32_t)(row*128 + (((ksc*2 + aseg) ^ swzA)*16)));
                }
                ldsm_x4t(bh4, sb + OFF_BH + brow);
                #pragma unroll
                for (int mi = 0; mi < 2; mi++) {
                    mma_h(acc[mi][0], ah[mi], &bh4[0]);
                    mma_h(acc[mi][1], ah[mi], &bh4[2]);
                }
            }
        }

        {
            const float* sBias = (const float*)(smq + OFF_BIAS) + jt*64;
            float b00 = sBias[jW + rq],      b01 = sBias[jW + rq + 8];
            float b10 = sBias[jW + 16 + rq], b11 = sBias[jW + 24 + rq];
            #pragma unroll
            for (int ni = 0; ni < 2; ni++) {
                acc[0][ni][0] += b00; acc[0][ni][1] += b00;
                acc[0][ni][2] += b01; acc[0][ni][3] += b01;
                acc[1][ni][0] += b10; acc[1][ni][1] += b10;
                acc[1][ni][2] += b11; acc[1][ni][3] += b11;
            }
        }

        float* stg = (float*)(smq + OFF_STG);
        #pragma unroll
        for (int mi = 0; mi < 2; mi++)
            #pragma unroll
            for (int ni = 0; ni < 2; ni++) {
                int j = jW + mi*16 + rq;
                int p = pW + ni*8 + c2;
                stg[p*STGP + j]         = acc[mi][ni][0];
                stg[(p+1)*STGP + j]     = acc[mi][ni][1];
                stg[p*STGP + j + 8]     = acc[mi][ni][2];
                stg[(p+1)*STGP + j + 8] = acc[mi][ni][3];
            }
        __syncthreads();

        #pragma unroll
        for (int k4 = 0; k4 < 4; k4++) {
            int idx = tid + k4*256;
            int pl = idx >> 4, jq = (idx & 15) * 4;
            float4 v = *(const float4*)&stg[pl*STGP + jq];
            __half2 h0 = __float22half2_rn(make_float2(v.x, v.y));
            __half2 h1 = __float22half2_rn(make_float2(v.z, v.w));
            uint2 hv = make_uint2(*(uint32_t*)&h0, *(uint32_t*)&h1);
            int p = pBase + pl;
            int h = p / WW, w = p - h*WW;
            size_t col = (size_t)(bz*WW + w)*HH + h;
            if (jt == 0)      *(uint2*)(g_Qhi + col*QKD + jq) = hv;
            else if (jt == 1) *(uint2*)(g_Khi + col*QKD + jq) = hv;
            else              *(uint2*)(g_Vhi + col*CC + (jt-2)*64 + jq) = hv;
        }
        __syncthreads();
    }
}

// ---------------- kernel 2: per-(b,w) column attention (3 CTA/SM) ------------
// V double-buffered (2 x 12KB); 64.5KB smem total.
#define AOFF_Q   0          // 12288
#define AOFF_K   12288      // ends 24576
#define AOFF_A   0          // fp16 96x104 (19968) overlays Q + dead K head
#define AOFF_V   24576      // 2 slots x 12288 (ends 49152)
#define AOFF_O   49152      // fp16 96x72 = 13824 (ends 62976)
#define AOFF_STAT 62976     // 3072 (ends 66048)
#define ATT_SMEM 66048
#define APITCH 208

__global__ __launch_bounds__(256, 3) void attn_mma_kernel() {
    extern __shared__ __align__(128) char sma[];
    uint32_t sb = smem_u32(sma);
    int tid = threadIdx.x, wid = tid >> 5, lane = tid & 31;
    int bw = blockIdx.x;
    int swz = lane & 7;
    const __half* Vh = g_Vhi + (size_t)bw*HH*CC;

    // ---- group 0: Qh, Kh
    {
        const __half* Qh = g_Qhi + (size_t)bw*HH*QKD;
        const __half* Kh = g_Khi + (size_t)bw*HH*QKD;
        for (int i = tid; i < 768; i += 256) {
            int h = i >> 3, sg = i & 7;
            uint32_t sw = (uint32_t)(h*128 + ((sg ^ (h & 7))*16));
            int go = h*QKD + sg*8;
            CP_ASYNC16(sb + AOFF_Q + sw, Qh + go);
            CP_ASYNC16(sb + AOFF_K + sw, Kh + go);
        }
        CP_COMMIT();
    }
    // ---- groups 1,2: V chunks 0,1 into slots 0,1
    #pragma unroll
    for (int pre = 0; pre < 2; pre++) {
        uint32_t dst = sb + AOFF_V + (uint32_t)(pre * 12288);
        for (int t = tid; t < 768; t += 256) {
            int g = t >> 3, sg = t & 7;
            uint32_t sw = (uint32_t)(g*128 + ((sg ^ (g & 7))*16));
            CP_ASYNC16(dst + sw, Vh + (size_t)g*CC + pre*64 + sg*8);
        }
        CP_COMMIT();
    }
    CP_WAIT2();          // Q/K resident (V0,V1 may still be in flight)
    __syncthreads();

    int warpM = wid & 1, warpN = wid >> 1;
    int m0 = warpM * 48;
    int n0 = warpN * 24;
    int rq = lane >> 2, c2 = (lane & 3) * 2;

    // ---- scores: warp tile 48m x 24n, 1 pass
    float acc[3][3][4] = {};
    #pragma unroll
    for (int ks = 0; ks < 4; ks++) {
        uint32_t af[3][4], bf4[4], bf2[2];
        #pragma unroll
        for (int mi = 0; mi < 3; mi++) {
            int row = m0 + (lane & 15) + mi*16;
            ldsm_x4(af[mi], sb + AOFF_Q + (uint32_t)(row*128 + (((ks*2 + (lane >> 4)) ^ swz)*16)));
        }
        {
            int row = n0 + ((lane >> 4) << 3) + (lane & 7);
            int seg = (ks*2 + ((lane >> 3) & 1)) ^ swz;
            ldsm_x4(bf4, sb + AOFF_K + (uint32_t)(row*128 + seg*16));
        }
        {
            int row = n0 + 16 + (lane & 7);
            int seg = (ks*2 + ((lane >> 3) & 1)) ^ swz;
            ldsm_x2(bf2, sb + AOFF_K + (uint32_t)(row*128 + seg*16));
        }
        #pragma unroll
        for (int mi = 0; mi < 3; mi++) {
            mma_h(acc[mi][0], af[mi], &bf4[0]);
            mma_h(acc[mi][1], af[mi], &bf4[2]);
            mma_h(acc[mi][2], af[mi], bf2);
        }
    }

    // ---- softmax
    float* pmax = (float*)(sma + AOFF_STAT);
    float* psum = (float*)(sma + AOFF_STAT + 1536);
    #pragma unroll
    for (int mi = 0; mi < 3; mi++) {
        float m0v = fmaxf(fmaxf(acc[mi][0][0], acc[mi][0][1]),
                          fmaxf(acc[mi][1][0], acc[mi][1][1]));
        m0v = fmaxf(m0v, fmaxf(acc[mi][2][0], acc[mi][2][1]));
        float m1v = fmaxf(fmaxf(acc[mi][0][2], acc[mi][0][3]),
                          fmaxf(acc[mi][1][2], acc[mi][1][3]));
        m1v = fmaxf(m1v, fmaxf(acc[mi][2][2], acc[mi][2][3]));
        m0v = fmaxf(m0v, __shfl_xor_sync(0xffffffffu, m0v, 1));
        m0v = fmaxf(m0v, __shfl_xor_sync(0xffffffffu, m0v, 2));
        m1v = fmaxf(m1v, __shfl_xor_sync(0xffffffffu, m1v, 1));
        m1v = fmaxf(m1v, __shfl_xor_sync(0xffffffffu, m1v, 2));
        if ((lane & 3) == 0) {
            pmax[warpN*96 + m0 + mi*16 + rq]     = m0v;
            pmax[warpN*96 + m0 + mi*16 + rq + 8] = m1v;
        }
    }
    __syncthreads();
    #pragma unroll
    for (int mi = 0; mi < 3; mi++) {
        #pragma unroll
        for (int hf = 0; hf < 2; hf++) {
            int row = m0 + mi*16 + rq + hf*8;
            float gm = fmaxf(fmaxf(pmax[row], pmax[96 + row]),
                             fmaxf(pmax[192 + row], pmax[288 + row]));
            float s = 0.f;
            #pragma unroll
            for (int nj = 0; nj < 3; nj++) {
                float e0 = __expf(acc[mi][nj][hf*2]     - gm);
                float e1 = __expf(acc[mi][nj][hf*2 + 1] - gm);
                acc[mi][nj][hf*2] = e0; acc[mi][nj][hf*2 + 1] = e1;
                s += e0 + e1;
            }
            s += __shfl_xor_sync(0xffffffffu, s, 1);
            s += __shfl_xor_sync(0xffffffffu, s, 2);
            if ((lane & 3) == 0) psum[warpN*96 + row] = s;
        }
    }
    __syncthreads();
    {
        __half* sA = (__half*)(sma + AOFF_A);
        #pragma unroll
        for (int mi = 0; mi < 3; mi++) {
            #pragma unroll
            for (int hf = 0; hf < 2; hf++) {
                int row = m0 + mi*16 + rq + hf*8;
                float tot = psum[row] + psum[96 + row] + psum[192 + row] + psum[288 + row];
                float inv = 1.0f / tot;
                #pragma unroll
                for (int nj = 0; nj < 3; nj++) {
                    __half2 a2 = __floats2half2_rn(acc[mi][nj][hf*2] * inv,
                                                   acc[mi][nj][hf*2 + 1] * inv);
                    *(__half2*)&sA[row*(APITCH/2) + n0 + nj*8 + c2] = a2;
                }
            }
        }
    }
    CP_WAIT1();          // V0 resident (V1 may be pending)
    __syncthreads();     // sA + V0 visible

    // ---- AV: 4 chunks of 64c, warp tile 48m x 16c, V double-buffered
    __half* Og = g_Ot + (size_t)bw*HH*CC;
    int cW = warpN * 16;
    int vseg = warpN * 2;

    #pragma unroll
    for (int ck = 0; ck < 4; ck++) {
        uint32_t vBase = sb + AOFF_V + (uint32_t)((ck & 1) * 12288);
        float vacc[3][2][4] = {};
        #pragma unroll
        for (int ks = 0; ks < 6; ks++) {
            uint32_t af[3][4], bh4[4];
            #pragma unroll
            for (int mi = 0; mi < 3; mi++) {
                int row = m0 + (lane & 15) + mi*16;
                ldsm_x4(af[mi], sb + AOFF_A + (uint32_t)(row*APITCH + ks*32 + (lane >> 4)*16));
            }
            {
                int row = ks*16 + (lane & 15);
                int seg = (vseg + (lane >> 4)) ^ swz;
                ldsm_x4t(bh4, vBase + (uint32_t)(row*128 + seg*16));
            }
            #pragma unroll
            for (int mi = 0; mi < 3; mi++) {
                mma_h(vacc[mi][0], af[mi], &bh4[0]);
                mma_h(vacc[mi][1], af[mi], &bh4[2]);
            }
        }
        __syncthreads();   // V-slot reads done + previous sO readers done

        // refill this slot with chunk ck+2 (if any)
        if (ck < 2) {
            uint32_t dst = sb + AOFF_V + (uint32_t)((ck & 1) * 12288);
            for (int t = tid; t < 768; t += 256) {
                int g = t >> 3, sg = t & 7;
                uint32_t sw = (uint32_t)(g*128 + ((sg ^ (g & 7))*16));
                CP_ASYNC16(dst + sw, Vh + (size_t)g*CC + (ck + 2)*64 + sg*8);
            }
            CP_COMMIT();
        }
        // ensure next chunk's data has arrived: pending = {V[ck+1], V[ck+2]?}
        if (ck == 0 || ck == 1) { CP_WAIT1(); } else if (ck == 2) { CP_WAIT0(); }

        __half* sO = (__half*)(sma + AOFF_O);   // pitch 72 halfs
        #pragma unroll
        for (int mi = 0; mi < 3; mi++)
            #pragma unroll
            for (int ni = 0; ni < 2; ni++) {
                int row = m0 + mi*16 + rq, col = cW + ni*8 + c2;
                *(__half2*)&sO[row*72 + col]     = __floats2half2_rn(vacc[mi][ni][0], vacc[mi][ni][1]);
                *(__half2*)&sO[(row+8)*72 + col] = __floats2half2_rn(vacc[mi][ni][2], vacc[mi][ni][3]);
            }
        __syncthreads();   // sO ready + next V slot visible to all threads

        for (int i = tid; i < 768; i += 256) {
            int h = i >> 3, c8 = (i & 7) * 8;
            *(uint4*)&Og[(size_t)h*CC + ck*64 + c8] = *(uint4*)&sO[h*72 + c8];
        }
    }
}

// ---------------- kernel 3: transpose back + residual -------------------------
__global__ __launch_bounds__(256) void out_kernel(const float* __restrict__ x,
                                                  const float* __restrict__ gamma,
                                                  float* __restrict__ out) {
    __shared__ float tile[32][66];
    int c0 = blockIdx.x * 64;
    int w0 = blockIdx.y * 32;
    int bh = blockIdx.z;
    int b = bh / HH, h = bh % HH;
    int tid = threadIdx.x;
    float gm = gamma[0];
    const __half* Ob = g_Ot + (size_t)b * WW * HH * CC;
    {
        int wl = tid >> 3, cs = (tid & 7) * 8;
        uint4 v = *(const uint4*)(Ob + (size_t)((w0 + wl)*HH + h)*CC + c0 + cs);
        __half2* hp = (__half2*)&v;
        #pragma unroll
        for (int i = 0; i < 4; i++) {
            float2 f = __half22float2(hp[i]);
            *(float2*)&tile[wl][cs + i*2] = f;
        }
    }
    __syncthreads();
    {
        int cl = tid >> 2, ws = (tid & 3) * 8;
        size_t base = (size_t)b*CC*PP + (size_t)(c0 + cl)*PP + (size_t)h*WW + w0 + ws;
        float4 x0 = *(const float4*)&x[base];
        float4 x1 = *(const float4*)&x[base + 4];
        float4 o0, o1;
        o0.x = gm*tile[ws+0][cl] + x0.x;
        o0.y = gm*tile[ws+1][cl] + x0.y;
        o0.z = gm*tile[ws+2][cl] + x0.z;
        o0.w = gm*tile[ws+3][cl] + x0.w;
        o1.x = gm*tile[ws+4][cl] + x1.x;
        o1.y = gm*tile[ws+5][cl] + x1.y;
        o1.z = gm*tile[ws+6][cl] + x1.z;
        o1.w = gm*tile[ws+7][cl] + x1.w;
        *(float4*)&out[base]     = o0;
        *(float4*)&out[base + 4] = o1;
    }
}

// ---------------- launcher ---------------------------------------------------
extern "C" void kernel_launch(void* const* d_in, const int* in_sizes, int n_in,
                              void* d_out, int out_size) {
    const float* x     = (const float*)d_in[0];
    const float* Wq    = (const float*)d_in[1];
    const float* bq    = (const float*)d_in[2];
    const float* Wk    = (const float*)d_in[3];
    const float* bk    = (const float*)d_in[4];
    const float* Wv    = (const float*)d_in[5];
    const float* bv    = (const float*)d_in[6];
    const float* gamma = (const float*)d_in[7];
    float* out = (float*)d_out;

    cudaFuncSetAttribute(qkv_mma_kernel, cudaFuncAttributeMaxDynamicSharedMemorySize, QKV_SMEM);
    cudaFuncSetAttribute(attn_mma_kernel, cudaFuncAttributeMaxDynamicSharedMemorySize, ATT_SMEM);

    prep_kernel<<<(JTOT*CC + 255)/256, 256>>>(Wq, bq, Wk, bk, Wv, bv);
    qkv_mma_kernel<<<dim3(PP/64, BB), 256, QKV_SMEM>>>(x);
    attn_mma_kernel<<<dim3(BB*WW), 256, ATT_SMEM>>>();
    out_kernel<<<dim3(CC/64, WW/32, BB*HH), dim3(256)>>>(x, gamma, out);
}